// round 9
// baseline (speedup 1.0000x reference)
#include <cuda_runtime.h>
#include <cuda_fp16.h>
#include <cstdint>

#define N_NODES 100000
#define N_EDGES 3200000
#define N_RELS  8
#define F_DIM   64

#define SCAN_BLK 1024
#define SCAN_NBLK ((N_NODES + SCAN_BLK - 1) / SCAN_BLK)   // 98

#define EBLOCKS ((N_EDGES + 255) / 256)                   // 12500
#define WCONV_BLOCKS ((N_RELS * 64 * 64 + 255) / 256)     // 128
#define XW_BLOCKS ((N_NODES + 63) / 64)                   // 1563

#define GATHER_BLOCKS 1184
#define GATHER_WARPS (GATHER_BLOCKS * 8)                  // 9472
#define SPAN ((N_EDGES + GATHER_WARPS - 1) / GATHER_WARPS) // 338

// fp16 per-relation transformed features: 102.4 MB
__device__ __half g_XWh[(size_t)N_RELS * N_NODES * F_DIM];
// fp16 transposed weights: g_Wht[r][n][k]
__device__ __half g_Wht[N_RELS * F_DIM * F_DIM];
// CSR-by-dst build
__device__ int g_count[N_NODES];
__device__ int g_tmp[N_NODES];
__device__ int g_start[N_NODES];
__device__ int g_cursor[N_NODES];
__device__ int g_blocktot[SCAN_NBLK];
__device__ int g_blockoff[SCAN_NBLK];
// 16B records grouped by dst: {src|rel<<17, bits(A), dst, 0}
__device__ uint4 g_recs4[N_EDGES];

// ---------------------------------------------------------------------------
// Fused: histogram over dst  +  W pre-convert/transpose (independent work)
// ---------------------------------------------------------------------------
__global__ __launch_bounds__(256) void hist_wconv_kernel(const int* __restrict__ dst,
                                                         const float* __restrict__ W) {
    int bx = blockIdx.x;
    if (bx < EBLOCKS) {
        int e = bx * 256 + threadIdx.x;
        if (e < N_EDGES) atomicAdd(&g_count[dst[e]], 1);
    } else {
        int i = (bx - EBLOCKS) * 256 + threadIdx.x;
        if (i < N_RELS * 64 * 64) {
            int r = i >> 12;
            int n = (i >> 6) & 63;
            int k = i & 63;
            g_Wht[i] = __float2half_rn(W[r * 4096 + k * 64 + n]);
        }
    }
}

// ---------------------------------------------------------------------------
// Scan (3 kernels)
// ---------------------------------------------------------------------------
__global__ __launch_bounds__(SCAN_BLK) void scan1_kernel() {
    __shared__ int s[SCAN_BLK];
    int t = threadIdx.x;
    int i = blockIdx.x * SCAN_BLK + t;
    int v = (i < N_NODES) ? g_count[i] : 0;
    s[t] = v;
    __syncthreads();
    for (int off = 1; off < SCAN_BLK; off <<= 1) {
        int add = (t >= off) ? s[t - off] : 0;
        __syncthreads();
        s[t] += add;
        __syncthreads();
    }
    if (i < N_NODES) g_tmp[i] = s[t];
    if (t == SCAN_BLK - 1) g_blocktot[blockIdx.x] = s[t];
}

__global__ __launch_bounds__(128) void scan2_kernel() {
    __shared__ int s[128];
    int t = threadIdx.x;
    s[t] = (t < SCAN_NBLK) ? g_blocktot[t] : 0;
    __syncthreads();
    for (int off = 1; off < 128; off <<= 1) {
        int add = (t >= off) ? s[t - off] : 0;
        __syncthreads();
        s[t] += add;
        __syncthreads();
    }
    if (t < SCAN_NBLK) g_blockoff[t] = s[t] - g_blocktot[t];
}

__global__ __launch_bounds__(SCAN_BLK) void scan3_kernel() {
    int i = blockIdx.x * SCAN_BLK + threadIdx.x;
    if (i < N_NODES) {
        int st = g_tmp[i] - g_count[i] + g_blockoff[blockIdx.x];
        g_start[i] = st;
        g_cursor[i] = st;
    }
}

// ---------------------------------------------------------------------------
// Fused: record scatter  +  XW GEMM (independent work, co-resident overlap)
// ---------------------------------------------------------------------------
__global__ __launch_bounds__(256) void scatter_xw_kernel(const float* __restrict__ A,
                                                         const int* __restrict__ src,
                                                         const int* __restrict__ dst,
                                                         const int* __restrict__ etype,
                                                         const float* __restrict__ X,
                                                         __half* __restrict__ XWh) {
    __shared__ __half Xh[64][72];
    __shared__ __half Wt[64][72];

    int bx = blockIdx.x;
    if (bx >= XW_BLOCKS) {
        // ---- scatter path ----
        int e = (bx - XW_BLOCKS) * 256 + threadIdx.x;
        if (e >= N_EDGES) return;
        int d = dst[e];
        int p = atomicAdd(&g_cursor[d], 1);
        unsigned key = (unsigned)src[e] | ((unsigned)etype[e] << 17);
        g_recs4[p] = make_uint4(key, __float_as_uint(A[e]), (unsigned)d, 0u);
        return;
    }

    // ---- xw path ----
    const int n0blk = bx * 64;

    for (int i = threadIdx.x; i < 64 * 32; i += 256) {
        int row = i >> 5, cp = i & 31;
        int n = n0blk + row;
        float2 v = (n < N_NODES)
            ? *reinterpret_cast<const float2*>(X + (size_t)n * 64 + cp * 2)
            : make_float2(0.0f, 0.0f);
        *reinterpret_cast<__half2*>(&Xh[row][cp * 2]) = __floats2half2_rn(v.x, v.y);
    }

    const int warp = threadIdx.x >> 5;
    const int lane = threadIdx.x & 31;
    const int g = lane >> 2;
    const int t = lane & 3;
    const int r0 = (warp & 3) * 16;
    const int ch = (warp >> 2) * 32;

    for (int r = 0; r < N_RELS; r++) {
        __syncthreads();
        for (int i = threadIdx.x; i < 64 * 32; i += 256) {
            int n = i >> 5, kp = i & 31;
            *reinterpret_cast<__half2*>(&Wt[n][kp * 2]) =
                *reinterpret_cast<const __half2*>(&g_Wht[r * 4096 + n * 64 + kp * 2]);
        }
        __syncthreads();

        float acc[4][4];
#pragma unroll
        for (int j = 0; j < 4; j++)
#pragma unroll
            for (int c = 0; c < 4; c++) acc[j][c] = 0.0f;

#pragma unroll
        for (int kk = 0; kk < 4; kk++) {
            const int k0 = kk * 16;
            uint32_t a0 = *reinterpret_cast<const uint32_t*>(&Xh[r0 + g    ][k0 + 2 * t    ]);
            uint32_t a1 = *reinterpret_cast<const uint32_t*>(&Xh[r0 + g + 8][k0 + 2 * t    ]);
            uint32_t a2 = *reinterpret_cast<const uint32_t*>(&Xh[r0 + g    ][k0 + 2 * t + 8]);
            uint32_t a3 = *reinterpret_cast<const uint32_t*>(&Xh[r0 + g + 8][k0 + 2 * t + 8]);
#pragma unroll
            for (int j = 0; j < 4; j++) {
                const int n0 = ch + j * 8;
                uint32_t b0 = *reinterpret_cast<const uint32_t*>(&Wt[n0 + g][k0 + 2 * t    ]);
                uint32_t b1 = *reinterpret_cast<const uint32_t*>(&Wt[n0 + g][k0 + 2 * t + 8]);
                asm volatile(
                    "mma.sync.aligned.m16n8k16.row.col.f32.f16.f16.f32 "
                    "{%0,%1,%2,%3}, {%4,%5,%6,%7}, {%8,%9}, {%0,%1,%2,%3};"
                    : "+f"(acc[j][0]), "+f"(acc[j][1]), "+f"(acc[j][2]), "+f"(acc[j][3])
                    : "r"(a0), "r"(a1), "r"(a2), "r"(a3), "r"(b0), "r"(b1));
            }
        }

        __half* base = XWh + (size_t)r * N_NODES * 64;
#pragma unroll
        for (int j = 0; j < 4; j++) {
            const int col = ch + j * 8 + 2 * t;
            const int row_a = n0blk + r0 + g;
            const int row_b = row_a + 8;
            __half2 lo = __floats2half2_rn(acc[j][0], acc[j][1]);
            __half2 hi = __floats2half2_rn(acc[j][2], acc[j][3]);
            if (row_a < N_NODES)
                *reinterpret_cast<__half2*>(base + (size_t)row_a * 64 + col) = lo;
            if (row_b < N_NODES)
                *reinterpret_cast<__half2*>(base + (size_t)row_b * 64 + col) = hi;
        }
    }
}

// ---------------------------------------------------------------------------
// Edge-balanced gather: each warp owns a contiguous SPAN of dst-grouped
// records. Interior nodes -> plain store; boundary nodes -> red.add.v2.
// ---------------------------------------------------------------------------
__device__ __forceinline__ void flush_node(float* __restrict__ Y, int d,
                                           int e0, int e1, int lane,
                                           float& acc0, float& acc1) {
    int st = g_start[d];
    int ct = g_count[d];
    float* p = Y + (size_t)d * 64 + 2 * lane;
    if (st >= e0 && st + ct <= e1) {
        *reinterpret_cast<float2*>(p) = make_float2(acc0, acc1);
    } else {
        asm volatile("red.global.add.v2.f32 [%0], {%1, %2};"
                     :: "l"(p), "f"(acc0), "f"(acc1) : "memory");
    }
    acc0 = 0.0f;
    acc1 = 0.0f;
}

__global__ __launch_bounds__(256) void gather_kernel(const __half* __restrict__ XWh,
                                                     float* __restrict__ Y) {
    const int lane = threadIdx.x & 31;
    const int wid = blockIdx.x * 8 + (threadIdx.x >> 5);

    const int e0 = wid * SPAN;
    if (e0 >= N_EDGES) return;
    int e1 = e0 + SPAN;
    if (e1 > N_EDGES) e1 = N_EDGES;

    int d_cur = (int)g_recs4[e0].z;
    float acc0 = 0.0f, acc1 = 0.0f;

    int i = e0;
    for (; i + 8 <= e1; i += 8) {
        uint4 rr[8];
#pragma unroll
        for (int q = 0; q < 8; q++) rr[q] = g_recs4[i + q];

        float2 f[8];
#pragma unroll
        for (int q = 0; q < 8; q++) {
            unsigned k = rr[q].x;
            size_t row = (size_t)(k >> 17) * N_NODES + (k & 0x1FFFF);
            __half2 h = *(reinterpret_cast<const __half2*>(XWh + row * 64) + lane);
            f[q] = __half22float2(h);
        }
#pragma unroll
        for (int q = 0; q < 8; q++) {
            int d = (int)rr[q].z;
            if (d != d_cur) {                       // uniform warp-wide branch
                flush_node(Y, d_cur, e0, e1, lane, acc0, acc1);
                d_cur = d;
            }
            float a = __uint_as_float(rr[q].y);
            acc0 = fmaf(f[q].x, a, acc0);
            acc1 = fmaf(f[q].y, a, acc1);
        }
    }
    for (; i < e1; i++) {
        uint4 r = g_recs4[i];
        int d = (int)r.z;
        if (d != d_cur) {
            flush_node(Y, d_cur, e0, e1, lane, acc0, acc1);
            d_cur = d;
        }
        unsigned k = r.x;
        float a = __uint_as_float(r.y);
        size_t row = (size_t)(k >> 17) * N_NODES + (k & 0x1FFFF);
        __half2 h = *(reinterpret_cast<const __half2*>(XWh + row * 64) + lane);
        float2 f = __half22float2(h);
        acc0 = fmaf(f.x, a, acc0);
        acc1 = fmaf(f.y, a, acc1);
    }
    flush_node(Y, d_cur, e0, e1, lane, acc0, acc1);
}

// ---------------------------------------------------------------------------
extern "C" void kernel_launch(void* const* d_in, const int* in_sizes, int n_in,
                              void* d_out, int out_size) {
    const float* X     = (const float*)d_in[0];
    const float* W     = (const float*)d_in[1];
    const float* A     = (const float*)d_in[2];
    const int*   src   = (const int*)d_in[3];
    const int*   dst   = (const int*)d_in[4];
    const int*   etype = (const int*)d_in[5];
    float* Y = (float*)d_out;

    __half* XWh = nullptr;
    cudaGetSymbolAddress((void**)&XWh, g_XWh);
    void* countp = nullptr;
    cudaGetSymbolAddress(&countp, g_count);

    cudaMemsetAsync(countp, 0, N_NODES * sizeof(int), 0);
    cudaMemsetAsync(Y, 0, (size_t)N_NODES * F_DIM * sizeof(float), 0);

    hist_wconv_kernel<<<EBLOCKS + WCONV_BLOCKS, 256>>>(dst, W);
    scan1_kernel<<<SCAN_NBLK, SCAN_BLK>>>();
    scan2_kernel<<<1, 128>>>();
    scan3_kernel<<<SCAN_NBLK, SCAN_BLK>>>();

    // scatter + XW GEMM co-resident (independent work)
    scatter_xw_kernel<<<XW_BLOCKS + EBLOCKS, 256>>>(A, src, dst, etype, X, XWh);

    // edge-balanced gather
    gather_kernel<<<GATHER_BLOCKS, 256>>>(XWh, Y);
}

// round 10
// speedup vs baseline: 1.2172x; 1.2172x over previous
#include <cuda_runtime.h>
#include <cuda_fp16.h>
#include <cstdint>

#define N_NODES 100000
#define N_EDGES 3200000
#define N_RELS  8
#define F_DIM   64

#define SCAN_BLK 1024
#define SCAN_NBLK ((N_NODES + SCAN_BLK - 1) / SCAN_BLK)   // 98

#define EBLOCKS ((N_EDGES + 255) / 256)                   // 12500
#define WCONV_BLOCKS ((N_RELS * 64 * 64 + 255) / 256)     // 128
#define XW_BLOCKS ((N_NODES + 63) / 64)                   // 1563

// fp16 per-relation transformed features: 102.4 MB
__device__ __half g_XWh[(size_t)N_RELS * N_NODES * F_DIM];
// fp16 transposed weights: g_Wht[r][n][k]
__device__ __half g_Wht[N_RELS * F_DIM * F_DIM];
// CSR-by-dst build
__device__ int g_count[N_NODES];
__device__ int g_tmp[N_NODES];
__device__ int g_start[N_NODES];
__device__ int g_cursor[N_NODES];
__device__ int g_blocktot[SCAN_NBLK];
__device__ int g_blockoff[SCAN_NBLK];
// packed edge records grouped by dst: lo32 = src | (rel<<17), hi32 = bits(A)
__device__ unsigned long long g_recs[N_EDGES];

// ---------------------------------------------------------------------------
// Fused: histogram over dst  +  W pre-convert/transpose (independent work)
// ---------------------------------------------------------------------------
__global__ __launch_bounds__(256) void hist_wconv_kernel(const int* __restrict__ dst,
                                                         const float* __restrict__ W) {
    int bx = blockIdx.x;
    if (bx < EBLOCKS) {
        int e = bx * 256 + threadIdx.x;
        if (e < N_EDGES) atomicAdd(&g_count[dst[e]], 1);
    } else {
        int i = (bx - EBLOCKS) * 256 + threadIdx.x;
        if (i < N_RELS * 64 * 64) {
            int r = i >> 12;
            int n = (i >> 6) & 63;
            int k = i & 63;
            g_Wht[i] = __float2half_rn(W[r * 4096 + k * 64 + n]);
        }
    }
}

// ---------------------------------------------------------------------------
// Scan (3 kernels)
// ---------------------------------------------------------------------------
__global__ __launch_bounds__(SCAN_BLK) void scan1_kernel() {
    __shared__ int s[SCAN_BLK];
    int t = threadIdx.x;
    int i = blockIdx.x * SCAN_BLK + t;
    int v = (i < N_NODES) ? g_count[i] : 0;
    s[t] = v;
    __syncthreads();
    for (int off = 1; off < SCAN_BLK; off <<= 1) {
        int add = (t >= off) ? s[t - off] : 0;
        __syncthreads();
        s[t] += add;
        __syncthreads();
    }
    if (i < N_NODES) g_tmp[i] = s[t];
    if (t == SCAN_BLK - 1) g_blocktot[blockIdx.x] = s[t];
}

__global__ __launch_bounds__(128) void scan2_kernel() {
    __shared__ int s[128];
    int t = threadIdx.x;
    s[t] = (t < SCAN_NBLK) ? g_blocktot[t] : 0;
    __syncthreads();
    for (int off = 1; off < 128; off <<= 1) {
        int add = (t >= off) ? s[t - off] : 0;
        __syncthreads();
        s[t] += add;
        __syncthreads();
    }
    if (t < SCAN_NBLK) g_blockoff[t] = s[t] - g_blocktot[t];
}

__global__ __launch_bounds__(SCAN_BLK) void scan3_kernel() {
    int i = blockIdx.x * SCAN_BLK + threadIdx.x;
    if (i < N_NODES) {
        int st = g_tmp[i] - g_count[i] + g_blockoff[blockIdx.x];
        g_start[i] = st;
        g_cursor[i] = st;
    }
}

// ---------------------------------------------------------------------------
// Fused: record scatter  +  XW GEMM (independent work, co-resident overlap)
// ---------------------------------------------------------------------------
__global__ __launch_bounds__(256) void scatter_xw_kernel(const float* __restrict__ A,
                                                         const int* __restrict__ src,
                                                         const int* __restrict__ dst,
                                                         const int* __restrict__ etype,
                                                         const float* __restrict__ X,
                                                         __half* __restrict__ XWh) {
    __shared__ __half Xh[64][72];
    __shared__ __half Wt[64][72];

    int bx = blockIdx.x;
    if (bx >= XW_BLOCKS) {
        // ---- scatter path ----
        int e = (bx - XW_BLOCKS) * 256 + threadIdx.x;
        if (e >= N_EDGES) return;
        int d = dst[e];
        int p = atomicAdd(&g_cursor[d], 1);
        unsigned key = (unsigned)src[e] | ((unsigned)etype[e] << 17);
        unsigned long long rec = (unsigned long long)key |
                                 ((unsigned long long)__float_as_uint(A[e]) << 32);
        g_recs[p] = rec;
        return;
    }

    // ---- xw path ----
    const int n0blk = bx * 64;

    for (int i = threadIdx.x; i < 64 * 32; i += 256) {
        int row = i >> 5, cp = i & 31;
        int n = n0blk + row;
        float2 v = (n < N_NODES)
            ? *reinterpret_cast<const float2*>(X + (size_t)n * 64 + cp * 2)
            : make_float2(0.0f, 0.0f);
        *reinterpret_cast<__half2*>(&Xh[row][cp * 2]) = __floats2half2_rn(v.x, v.y);
    }

    const int warp = threadIdx.x >> 5;
    const int lane = threadIdx.x & 31;
    const int g = lane >> 2;
    const int t = lane & 3;
    const int r0 = (warp & 3) * 16;
    const int ch = (warp >> 2) * 32;

    for (int r = 0; r < N_RELS; r++) {
        __syncthreads();
        for (int i = threadIdx.x; i < 64 * 32; i += 256) {
            int n = i >> 5, kp = i & 31;
            *reinterpret_cast<__half2*>(&Wt[n][kp * 2]) =
                *reinterpret_cast<const __half2*>(&g_Wht[r * 4096 + n * 64 + kp * 2]);
        }
        __syncthreads();

        float acc[4][4];
#pragma unroll
        for (int j = 0; j < 4; j++)
#pragma unroll
            for (int c = 0; c < 4; c++) acc[j][c] = 0.0f;

#pragma unroll
        for (int kk = 0; kk < 4; kk++) {
            const int k0 = kk * 16;
            uint32_t a0 = *reinterpret_cast<const uint32_t*>(&Xh[r0 + g    ][k0 + 2 * t    ]);
            uint32_t a1 = *reinterpret_cast<const uint32_t*>(&Xh[r0 + g + 8][k0 + 2 * t    ]);
            uint32_t a2 = *reinterpret_cast<const uint32_t*>(&Xh[r0 + g    ][k0 + 2 * t + 8]);
            uint32_t a3 = *reinterpret_cast<const uint32_t*>(&Xh[r0 + g + 8][k0 + 2 * t + 8]);
#pragma unroll
            for (int j = 0; j < 4; j++) {
                const int n0 = ch + j * 8;
                uint32_t b0 = *reinterpret_cast<const uint32_t*>(&Wt[n0 + g][k0 + 2 * t    ]);
                uint32_t b1 = *reinterpret_cast<const uint32_t*>(&Wt[n0 + g][k0 + 2 * t + 8]);
                asm volatile(
                    "mma.sync.aligned.m16n8k16.row.col.f32.f16.f16.f32 "
                    "{%0,%1,%2,%3}, {%4,%5,%6,%7}, {%8,%9}, {%0,%1,%2,%3};"
                    : "+f"(acc[j][0]), "+f"(acc[j][1]), "+f"(acc[j][2]), "+f"(acc[j][3])
                    : "r"(a0), "r"(a1), "r"(a2), "r"(a3), "r"(b0), "r"(b1));
            }
        }

        __half* base = XWh + (size_t)r * N_NODES * 64;
#pragma unroll
        for (int j = 0; j < 4; j++) {
            const int col = ch + j * 8 + 2 * t;
            const int row_a = n0blk + r0 + g;
            const int row_b = row_a + 8;
            __half2 lo = __floats2half2_rn(acc[j][0], acc[j][1]);
            __half2 hi = __floats2half2_rn(acc[j][2], acc[j][3]);
            if (row_a < N_NODES)
                *reinterpret_cast<__half2*>(base + (size_t)row_a * 64 + col) = lo;
            if (row_b < N_NODES)
                *reinterpret_cast<__half2*>(base + (size_t)row_b * 64 + col) = hi;
        }
    }
}

// ---------------------------------------------------------------------------
// Gather (R8 winner): one warp per dst node, 8-edge compile-time unroll,
// branch-free hot loop, no shuffles.
// ---------------------------------------------------------------------------
__global__ __launch_bounds__(256) void gather_kernel(const __half* __restrict__ XWh,
                                                     float* __restrict__ Y) {
    const int node = blockIdx.x * 8 + (threadIdx.x >> 5);
    if (node >= N_NODES) return;
    const int lane = threadIdx.x & 31;

    const int s = g_start[node];
    const int end = s + g_count[node];

    float acc0 = 0.0f, acc1 = 0.0f;

    int i = s;
    for (; i + 8 <= end; i += 8) {
        unsigned long long rr[8];
#pragma unroll
        for (int q = 0; q < 8; q++) rr[q] = g_recs[i + q];

        float2 f[8];
        float a[8];
#pragma unroll
        for (int q = 0; q < 8; q++) {
            unsigned k = (unsigned)rr[q];
            a[q] = __uint_as_float((unsigned)(rr[q] >> 32));
            size_t row = (size_t)(k >> 17) * N_NODES + (k & 0x1FFFF);
            __half2 h = *(reinterpret_cast<const __half2*>(XWh + row * 64) + lane);
            f[q] = __half22float2(h);
        }
#pragma unroll
        for (int q = 0; q < 8; q++) {
            acc0 = fmaf(f[q].x, a[q], acc0);
            acc1 = fmaf(f[q].y, a[q], acc1);
        }
    }
    for (; i < end; i++) {
        unsigned long long r0 = g_recs[i];
        unsigned k0 = (unsigned)r0;
        float a0 = __uint_as_float((unsigned)(r0 >> 32));
        size_t row0 = (size_t)(k0 >> 17) * N_NODES + (k0 & 0x1FFFF);
        __half2 h0 = *(reinterpret_cast<const __half2*>(XWh + row0 * 64) + lane);
        float2 f0 = __half22float2(h0);
        acc0 = fmaf(f0.x, a0, acc0);
        acc1 = fmaf(f0.y, a0, acc1);
    }

    *reinterpret_cast<float2*>(Y + (size_t)node * 64 + 2 * lane) =
        make_float2(acc0, acc1);
}

// ---------------------------------------------------------------------------
extern "C" void kernel_launch(void* const* d_in, const int* in_sizes, int n_in,
                              void* d_out, int out_size) {
    const float* X     = (const float*)d_in[0];
    const float* W     = (const float*)d_in[1];
    const float* A     = (const float*)d_in[2];
    const int*   src   = (const int*)d_in[3];
    const int*   dst   = (const int*)d_in[4];
    const int*   etype = (const int*)d_in[5];
    float* Y = (float*)d_out;

    __half* XWh = nullptr;
    cudaGetSymbolAddress((void**)&XWh, g_XWh);
    void* countp = nullptr;
    cudaGetSymbolAddress(&countp, g_count);

    cudaMemsetAsync(countp, 0, N_NODES * sizeof(int), 0);

    hist_wconv_kernel<<<EBLOCKS + WCONV_BLOCKS, 256>>>(dst, W);
    scan1_kernel<<<SCAN_NBLK, SCAN_BLK>>>();
    scan2_kernel<<<1, 128>>>();
    scan3_kernel<<<SCAN_NBLK, SCAN_BLK>>>();

    // scatter + XW GEMM co-resident (independent work)
    scatter_xw_kernel<<<XW_BLOCKS + EBLOCKS, 256>>>(A, src, dst, etype, X, XWh);

    // warp-per-node gather (writes every Y element; no memset needed)
    gather_kernel<<<(N_NODES + 7) / 8, 256>>>(XWh, Y);
}